// round 1
// baseline (speedup 1.0000x reference)
#include <cuda_runtime.h>
#include <cuda_bf16.h>

// Fused 13-tap depthwise conv: (4th-order FD 2nd-derivative stencil, 5 taps)
// composed with (Gaussian smoothing, 9 taps). Both are cross-correlations
// with symmetric kernels, so the composition is a single 13-tap correlation:
//   z[t] = sum_{k=0..12} w[k] * x[t+k],  w[k] = sum_i fd[i]*gauss[k-i]
//
// Shapes: x [8,4,1048576] fp32 -> out [8,4,1048564] fp32 (32 rows).
// Row output length 1048564 = 4*262141 exactly, so the whole output is a
// dense array of float4 groups; group gid writes out4[gid] and reads the
// aligned input window in[row*T + 4g .. +15] (4 float4 loads, always
// in-bounds since 1048560+15 = T-1... actually 1048575 = T-1).

#define T_IN 1048576
#define T_OUT 1048564
#define G_PER_ROW 262141          // T_OUT / 4
#define N_ROWS 32
#define TOTAL_GROUPS (N_ROWS * G_PER_ROW)   // 8388512
#define NTHREADS 256

__device__ float g_w13[13];

__global__ void prep_weights_kernel(const float* __restrict__ fd,
                                    const float* __restrict__ gs) {
    int k = threadIdx.x;
    if (k < 13) {
        float s = 0.0f;
        #pragma unroll
        for (int i = 0; i < 5; i++) {
            int j = k - i;
            if (j >= 0 && j < 9) s += fd[i] * gs[j];
        }
        g_w13[k] = s;
    }
}

__global__ __launch_bounds__(NTHREADS)
void fused_conv13_kernel(const float* __restrict__ x,
                         float4* __restrict__ out) {
    __shared__ float ws[13];
    if (threadIdx.x < 13) ws[threadIdx.x] = g_w13[threadIdx.x];
    __syncthreads();

    int gid = blockIdx.x * NTHREADS + threadIdx.x;
    if (gid >= TOTAL_GROUPS) return;

    int row = gid / G_PER_ROW;
    int g   = gid - row * G_PER_ROW;

    const float4* p4 = (const float4*)(x + (size_t)row * T_IN) + g;

    float a[16];
    #pragma unroll
    for (int v = 0; v < 4; v++) {
        float4 t = __ldg(p4 + v);
        a[4*v + 0] = t.x; a[4*v + 1] = t.y;
        a[4*v + 2] = t.z; a[4*v + 3] = t.w;
    }

    float w[13];
    #pragma unroll
    for (int k = 0; k < 13; k++) w[k] = ws[k];

    float r0 = 0.f, r1 = 0.f, r2 = 0.f, r3 = 0.f;
    #pragma unroll
    for (int k = 0; k < 13; k++) {
        r0 = fmaf(w[k], a[k + 0], r0);
        r1 = fmaf(w[k], a[k + 1], r1);
        r2 = fmaf(w[k], a[k + 2], r2);
        r3 = fmaf(w[k], a[k + 3], r3);
    }

    float4 o; o.x = r0; o.y = r1; o.z = r2; o.w = r3;
    out[gid] = o;
}

extern "C" void kernel_launch(void* const* d_in, const int* in_sizes, int n_in,
                              void* d_out, int out_size) {
    const float* x  = (const float*)d_in[0];   // [8,4,1048576]
    const float* fd = (const float*)d_in[1];   // [5]
    const float* gs = (const float*)d_in[2];   // [9]
    float4* out = (float4*)d_out;              // [8,4,1048564] as float4 groups

    prep_weights_kernel<<<1, 32>>>(fd, gs);

    int nblocks = (TOTAL_GROUPS + NTHREADS - 1) / NTHREADS;  // 32768
    fused_conv13_kernel<<<nblocks, NTHREADS>>>(x, out);
}

// round 4
// speedup vs baseline: 1.2280x; 1.2280x over previous
#include <cuda_runtime.h>
#include <cuda_bf16.h>

// Fused 13-tap depthwise conv (FD-5 composed with Gauss-9).
//   z[t] = sum_{k=0..12} w[k] * x[t+k]
// x [8,4,1048576] fp32 -> out [8,4,1048564] fp32 (32 independent rows).
//
// R2 strategy: the L1TEX data path was the bottleneck (90.6%) due to 4x
// redundant overlapping float4 loads + per-thread broadcast LDS of weights.
// Now each thread loads exactly ONE coalesced float4 and receives the
// 12-float halo from neighbor lanes via __shfl_down_sync (SHFL pipe, not
// L1 data path). Lanes 29-31 patch the out-of-warp halo with predicated
// loads (L1-hot). Weights live in registers, loaded once per warp; each
// warp loops over 4 chunks to amortize.

#define T_IN 1048576
#define G_IN 262144              // float4 groups per input row
#define G_OUT 262141             // float4 groups per output row (1048564/4)
#define N_ROWS 32
#define WARPS_PER_BLOCK 8
#define CHUNKS_PER_WARP 4
#define BLOCKS_X 256             // 256 * 8 * 4 = 8192 chunks = ceil(262141/32)

__device__ float g_w13[13];

__global__ void prep_weights_kernel(const float* __restrict__ fd,
                                    const float* __restrict__ gs) {
    int k = threadIdx.x;
    if (k < 13) {
        float s = 0.0f;
        #pragma unroll
        for (int i = 0; i < 5; i++) {
            int j = k - i;
            if (j >= 0 && j < 9) s += fd[i] * gs[j];
        }
        g_w13[k] = s;
    }
}

__device__ __forceinline__ float4 shfl_down_f4(float4 v, int delta) {
    float4 r;
    r.x = __shfl_down_sync(0xffffffffu, v.x, delta);
    r.y = __shfl_down_sync(0xffffffffu, v.y, delta);
    r.z = __shfl_down_sync(0xffffffffu, v.z, delta);
    r.w = __shfl_down_sync(0xffffffffu, v.w, delta);
    return r;
}

__global__ __launch_bounds__(256)
void fused_conv13_shfl_kernel(const float* __restrict__ x,
                              float4* __restrict__ out) {
    const int warp = threadIdx.x >> 5;
    const int lane = threadIdx.x & 31;
    const int row  = blockIdx.y;

    const float4* __restrict__ in4 = (const float4*)(x + (size_t)row * T_IN);
    float4* __restrict__ out4 = out + (size_t)row * G_OUT;

    // Weights into registers, once per thread (13 broadcast L1-hit loads,
    // amortized over CHUNKS_PER_WARP chunks).
    float w[13];
    #pragma unroll
    for (int k = 0; k < 13; k++) w[k] = g_w13[k];

    const int chunk0 = (blockIdx.x * WARPS_PER_BLOCK + warp) * CHUNKS_PER_WARP;

    #pragma unroll
    for (int i = 0; i < CHUNKS_PER_WARP; i++) {
        const int g0 = (chunk0 + i) << 5;     // chunk base group
        const int g  = g0 + lane;             // this thread's output group
        // fast: all halo loads (up to g0+34) in-bounds AND all 32 outputs valid
        const bool fast = (g0 + 35) <= G_IN;  // g0 <= 262109

        float4 v0 = in4[g];                   // always in-bounds (g <= 262143)

        // Halo via shuffle: v_k = float4 group g+k (valid for lane <= 31-k)
        float4 v1 = shfl_down_f4(v0, 1);
        float4 v2 = shfl_down_f4(v0, 2);
        float4 v3 = shfl_down_f4(v0, 3);

        if (fast) {
            // Patch lanes whose shuffle fell off the warp edge (L1-hot loads)
            if (lane >= 29) {
                v3 = in4[g + 3];
                if (lane >= 30) v2 = in4[g + 2];
                if (lane == 31) v1 = in4[g + 1];
            }
        }
        // slow chunk (last of each row): lanes 29-31 have garbage halo but
        // their outputs (g >= 262141) are never stored; lane 28 and below
        // get everything via shuffle from valid v0's.

        float a0=v0.x, a1=v0.y, a2=v0.z, a3=v0.w;
        float a4=v1.x, a5=v1.y, a6=v1.z, a7=v1.w;
        float a8=v2.x, a9=v2.y, a10=v2.z, a11=v2.w;
        float a12=v3.x, a13=v3.y, a14=v3.z, a15=v3.w;

        float r0, r1, r2, r3;
        r0 = w[0]*a0;  r1 = w[0]*a1;  r2 = w[0]*a2;  r3 = w[0]*a3;
        r0 = fmaf(w[1],a1,r0);  r1 = fmaf(w[1],a2,r1);  r2 = fmaf(w[1],a3,r2);  r3 = fmaf(w[1],a4,r3);
        r0 = fmaf(w[2],a2,r0);  r1 = fmaf(w[2],a3,r1);  r2 = fmaf(w[2],a4,r2);  r3 = fmaf(w[2],a5,r3);
        r0 = fmaf(w[3],a3,r0);  r1 = fmaf(w[3],a4,r1);  r2 = fmaf(w[3],a5,r2);  r3 = fmaf(w[3],a6,r3);
        r0 = fmaf(w[4],a4,r0);  r1 = fmaf(w[4],a5,r1);  r2 = fmaf(w[4],a6,r2);  r3 = fmaf(w[4],a7,r3);
        r0 = fmaf(w[5],a5,r0);  r1 = fmaf(w[5],a6,r1);  r2 = fmaf(w[5],a7,r2);  r3 = fmaf(w[5],a8,r3);
        r0 = fmaf(w[6],a6,r0);  r1 = fmaf(w[6],a7,r1);  r2 = fmaf(w[6],a8,r2);  r3 = fmaf(w[6],a9,r3);
        r0 = fmaf(w[7],a7,r0);  r1 = fmaf(w[7],a8,r1);  r2 = fmaf(w[7],a9,r2);  r3 = fmaf(w[7],a10,r3);
        r0 = fmaf(w[8],a8,r0);  r1 = fmaf(w[8],a9,r1);  r2 = fmaf(w[8],a10,r2); r3 = fmaf(w[8],a11,r3);
        r0 = fmaf(w[9],a9,r0);  r1 = fmaf(w[9],a10,r1); r2 = fmaf(w[9],a11,r2); r3 = fmaf(w[9],a12,r3);
        r0 = fmaf(w[10],a10,r0);r1 = fmaf(w[10],a11,r1);r2 = fmaf(w[10],a12,r2);r3 = fmaf(w[10],a13,r3);
        r0 = fmaf(w[11],a11,r0);r1 = fmaf(w[11],a12,r1);r2 = fmaf(w[11],a13,r2);r3 = fmaf(w[11],a14,r3);
        r0 = fmaf(w[12],a12,r0);r1 = fmaf(w[12],a13,r1);r2 = fmaf(w[12],a14,r2);r3 = fmaf(w[12],a15,r3);

        float4 o; o.x = r0; o.y = r1; o.z = r2; o.w = r3;
        if (fast) {
            out4[g] = o;
        } else if (g < G_OUT) {
            out4[g] = o;
        }
    }
}

extern "C" void kernel_launch(void* const* d_in, const int* in_sizes, int n_in,
                              void* d_out, int out_size) {
    const float* x  = (const float*)d_in[0];   // [8,4,1048576]
    const float* fd = (const float*)d_in[1];   // [5]
    const float* gs = (const float*)d_in[2];   // [9]
    float4* out = (float4*)d_out;              // [8,4,1048564] as float4 groups

    prep_weights_kernel<<<1, 32>>>(fd, gs);

    dim3 grid(BLOCKS_X, N_ROWS);
    fused_conv13_shfl_kernel<<<grid, 256>>>(x, out);
}

// round 7
// speedup vs baseline: 1.5180x; 1.2362x over previous
#include <cuda_runtime.h>
#include <cuda_bf16.h>

// Fused 13-tap depthwise conv (FD-5 composed with Gauss-9).
//   z[t] = sum_{k=0..12} w[k] * x[t+k]
// x [8,4,1048576] fp32 -> out [8,4,1048564] fp32 (32 independent rows).
//
// R4: latency-bound fix. All 4 chunk LDG.128s issue back-to-back at the top
// (MLP_p1=4) before any shuffle consumes them; weight prep is folded into the
// main kernel (smem) to kill the extra launch. Halo still via shfl_down
// (keeps L1 data-path traffic at ~1 load + 1 store per 16B output).

#define T_IN 1048576
#define G_IN 262144              // float4 groups per input row
#define G_OUT 262141             // float4 groups per output row (1048564/4)
#define N_ROWS 32
#define WARPS_PER_BLOCK 8
#define CHUNKS_PER_WARP 4
#define BLOCKS_X 256             // 256*8*4 = 8192 chunks = ceil(262141/32)

__device__ __forceinline__ float4 shfl_down_f4(float4 v, int delta) {
    float4 r;
    r.x = __shfl_down_sync(0xffffffffu, v.x, delta);
    r.y = __shfl_down_sync(0xffffffffu, v.y, delta);
    r.z = __shfl_down_sync(0xffffffffu, v.z, delta);
    r.w = __shfl_down_sync(0xffffffffu, v.w, delta);
    return r;
}

__global__ __launch_bounds__(256)
void fused_conv13_kernel(const float* __restrict__ x,
                         float4* __restrict__ out,
                         const float* __restrict__ fd,
                         const float* __restrict__ gs) {
    __shared__ float ws[13];

    const int warp = threadIdx.x >> 5;
    const int lane = threadIdx.x & 31;
    const int row  = blockIdx.y;

    // Composite 13-tap weights: w[k] = sum_i fd[i]*gauss[k-i].
    // Computed per block (tiny, fd/gs are L2-hot broadcasts).
    if (threadIdx.x < 13) {
        int k = threadIdx.x;
        float s = 0.0f;
        #pragma unroll
        for (int i = 0; i < 5; i++) {
            int j = k - i;
            if (j >= 0 && j < 9) s += fd[i] * gs[j];
        }
        ws[k] = s;
    }
    __syncthreads();

    const float4* __restrict__ in4 = (const float4*)(x + (size_t)row * T_IN);
    float4* __restrict__ out4 = out + (size_t)row * G_OUT;

    const int chunk0 = (blockIdx.x * WARPS_PER_BLOCK + warp) * CHUNKS_PER_WARP;

    // ---- Phase 1: batch all primary loads (MLP = 4) ----
    int gbase[CHUNKS_PER_WARP];
    float4 v0[CHUNKS_PER_WARP];
    #pragma unroll
    for (int i = 0; i < CHUNKS_PER_WARP; i++) {
        gbase[i] = (chunk0 + i) << 5;
        v0[i] = in4[gbase[i] + lane];     // g <= 262143, always in-bounds
    }

    float w[13];
    #pragma unroll
    for (int k = 0; k < 13; k++) w[k] = ws[k];

    // ---- Phase 2: per-chunk halo + FMA + store ----
    #pragma unroll
    for (int i = 0; i < CHUNKS_PER_WARP; i++) {
        const int g0 = gbase[i];
        const int g  = g0 + lane;
        const bool fast = (g0 + 35) <= G_IN;   // whole chunk + halo in-bounds

        float4 v1 = shfl_down_f4(v0[i], 1);
        float4 v2 = shfl_down_f4(v0[i], 2);
        float4 v3 = shfl_down_f4(v0[i], 3);

        if (fast) {
            // Lanes whose shuffle fell off the warp edge: L1-hot patch loads
            if (lane >= 29) {
                v3 = in4[g + 3];
                if (lane >= 30) v2 = in4[g + 2];
                if (lane == 31) v1 = in4[g + 1];
            }
        }
        // slow chunk (row tail): lanes 29-31 have garbage halo but their
        // outputs (g >= G_OUT) are never stored.

        float a0=v0[i].x, a1=v0[i].y, a2=v0[i].z, a3=v0[i].w;
        float a4=v1.x,  a5=v1.y,  a6=v1.z,  a7=v1.w;
        float a8=v2.x,  a9=v2.y,  a10=v2.z, a11=v2.w;
        float a12=v3.x, a13=v3.y, a14=v3.z, a15=v3.w;

        float r0, r1, r2, r3;
        r0 = w[0]*a0;  r1 = w[0]*a1;  r2 = w[0]*a2;  r3 = w[0]*a3;
        r0 = fmaf(w[1],a1,r0);   r1 = fmaf(w[1],a2,r1);   r2 = fmaf(w[1],a3,r2);   r3 = fmaf(w[1],a4,r3);
        r0 = fmaf(w[2],a2,r0);   r1 = fmaf(w[2],a3,r1);   r2 = fmaf(w[2],a4,r2);   r3 = fmaf(w[2],a5,r3);
        r0 = fmaf(w[3],a3,r0);   r1 = fmaf(w[3],a4,r1);   r2 = fmaf(w[3],a5,r2);   r3 = fmaf(w[3],a6,r3);
        r0 = fmaf(w[4],a4,r0);   r1 = fmaf(w[4],a5,r1);   r2 = fmaf(w[4],a6,r2);   r3 = fmaf(w[4],a7,r3);
        r0 = fmaf(w[5],a5,r0);   r1 = fmaf(w[5],a6,r1);   r2 = fmaf(w[5],a7,r2);   r3 = fmaf(w[5],a8,r3);
        r0 = fmaf(w[6],a6,r0);   r1 = fmaf(w[6],a7,r1);   r2 = fmaf(w[6],a8,r2);   r3 = fmaf(w[6],a9,r3);
        r0 = fmaf(w[7],a7,r0);   r1 = fmaf(w[7],a8,r1);   r2 = fmaf(w[7],a9,r2);   r3 = fmaf(w[7],a10,r3);
        r0 = fmaf(w[8],a8,r0);   r1 = fmaf(w[8],a9,r1);   r2 = fmaf(w[8],a10,r2);  r3 = fmaf(w[8],a11,r3);
        r0 = fmaf(w[9],a9,r0);   r1 = fmaf(w[9],a10,r1);  r2 = fmaf(w[9],a11,r2);  r3 = fmaf(w[9],a12,r3);
        r0 = fmaf(w[10],a10,r0); r1 = fmaf(w[10],a11,r1); r2 = fmaf(w[10],a12,r2); r3 = fmaf(w[10],a13,r3);
        r0 = fmaf(w[11],a11,r0); r1 = fmaf(w[11],a12,r1); r2 = fmaf(w[11],a13,r2); r3 = fmaf(w[11],a14,r3);
        r0 = fmaf(w[12],a12,r0); r1 = fmaf(w[12],a13,r1); r2 = fmaf(w[12],a14,r2); r3 = fmaf(w[12],a15,r3);

        float4 o; o.x = r0; o.y = r1; o.z = r2; o.w = r3;
        if (fast) {
            out4[g] = o;
        } else if (g < G_OUT) {
            out4[g] = o;
        }
    }
}

extern "C" void kernel_launch(void* const* d_in, const int* in_sizes, int n_in,
                              void* d_out, int out_size) {
    const float* x  = (const float*)d_in[0];   // [8,4,1048576]
    const float* fd = (const float*)d_in[1];   // [5]
    const float* gs = (const float*)d_in[2];   // [9]
    float4* out = (float4*)d_out;              // [8,4,1048564] as float4 groups

    dim3 grid(BLOCKS_X, N_ROWS);
    fused_conv13_kernel<<<grid, 256>>>(x, out, fd, gs);
}